// round 1
// baseline (speedup 1.0000x reference)
#include <cuda_runtime.h>
#include <math.h>

// Problem constants (dataset is fixed)
#define NMAX   200000
#define F      256
#define KGM    8         // K (gaussian mixture components)
#define M      128
#define KM     1024      // K*M
#define ATT    128

// kernel-1 tiling
#define TB     512       // threads per block
#define NODES  32        // nodes per block
#define KC     4         // k-chunk of g held in smem

// scratch (static device allocations are the sanctioned scratch mechanism)
__device__ float g_H[(size_t)NMAX * M];      // H[n, m]
__device__ float g_scores[NMAX];             // per-node attention score
__device__ int   g_is64;                     // batch dtype flag

// ---------------------------------------------------------------------------
// batch dtype sniffer: if batch is int64, int32-word at index n-1 (odd) is the
// high word of element (n-1)/2 == 0. If int32, it's the max graph id (!=0).
// ---------------------------------------------------------------------------
__global__ void sniff_kernel(const int* __restrict__ batch32, int n) {
    g_is64 = (batch32[n - 1] == 0) ? 1 : 0;
}

__device__ __forceinline__ int batch_at(const void* b, int i, int is64) {
    if (is64) return (int)((const long long*)b)[i];
    return ((const int*)b)[i];
}

// ---------------------------------------------------------------------------
// Kernel 1: per-node fused compute.
//   out[n,1024] = x[n,:] @ g            (fp32 GEMM, 32 nodes x 1024 cols/block)
//   gauss chain -> H[n,128]
//   a = tanh(H @ w1^T); score = a . w2
// Thread map (GEMM): tc = tid&63 (64 col threads), tn = tid>>6 (8 groups of 4
// rows). Thread owns cols {tc + 64*j, j=0..15}; since col = k*128+m, that is
// exactly k=0..7 for m=tc (j even) and m=tc+64 (j odd) -> gaussian sum over K
// is thread-local.
// ---------------------------------------------------------------------------
__global__ __launch_bounds__(TB, 1)
void node_kernel(const float* __restrict__ x,
                 const float* __restrict__ g,
                 const float* __restrict__ mu,
                 const float* __restrict__ sigma,
                 const float* __restrict__ w1,
                 const float* __restrict__ w2,
                 float* __restrict__ Hout,
                 float* __restrict__ scores,
                 int n)
{
    __shared__ float sbuf[4352];            // g chunk [KC][1024] (16KB) reused as w1 chunk [128][33]
    __shared__ float sx[NODES][KC];
    __shared__ float sH[NODES][M];

    const int tid = threadIdx.x;
    const int tc  = tid & 63;
    const int tn  = tid >> 6;               // 0..7
    const int node0 = blockIdx.x * NODES;

    float acc[4][16];
    #pragma unroll
    for (int ri = 0; ri < 4; ri++)
        #pragma unroll
        for (int j = 0; j < 16; j++) acc[ri][j] = 0.f;

    // ---- GEMM: out = x @ g over 64 k-chunks of KC=4 ----
    for (int kk = 0; kk < F; kk += KC) {
        __syncthreads();
        {   // load g chunk: KC*1024 floats = 1024 float4
            const float4* gsrc = (const float4*)(g + (size_t)kk * KM);
            float4* dst = (float4*)sbuf;
            #pragma unroll
            for (int i = 0; i < (KC * KM) / 4 / TB; i++)
                dst[tid + i * TB] = gsrc[tid + i * TB];
        }
        if (tid < NODES * KC) {             // load x tile 32 x 4
            int r = tid / KC, c = tid % KC;
            int nr = node0 + r;
            sx[r][c] = (nr < n) ? x[(size_t)nr * F + kk + c] : 0.f;
        }
        __syncthreads();

        #pragma unroll
        for (int k = 0; k < KC; k++) {
            float xv[4];
            #pragma unroll
            for (int ri = 0; ri < 4; ri++) xv[ri] = sx[tn * 4 + ri][k];
            float gv[16];
            #pragma unroll
            for (int j = 0; j < 16; j++) gv[j] = sbuf[k * KM + tc + 64 * j];
            #pragma unroll
            for (int ri = 0; ri < 4; ri++)
                #pragma unroll
                for (int j = 0; j < 16; j++)
                    acc[ri][j] = fmaf(xv[ri], gv[j], acc[ri][j]);
        }
    }

    // ---- Gaussian chain -> H (thread-local over K) ----
    float muv[16], s2v[16];
    #pragma unroll
    for (int j = 0; j < 16; j++) {
        int kk2 = j >> 1;
        int m   = tc + 64 * (j & 1);
        float s = sigma[kk2 * M + m];
        muv[j] = mu[kk2 * M + m];
        s2v[j] = 1e-15f + s * s;
    }
    #pragma unroll
    for (int ri = 0; ri < 4; ri++) {
        float Ha = 0.f, Hb = 0.f;
        #pragma unroll
        for (int j = 0; j < 16; j++) {
            float o = acc[ri][j];
            float d = o - muv[j];
            float gs = expf(-0.5f * d * d / s2v[j]);
            if (j & 1) Hb = fmaf(o, gs, Hb);
            else       Ha = fmaf(o, gs, Ha);
        }
        int r = tn * 4 + ri;
        sH[r][tc]      = Ha;
        sH[r][tc + 64] = Hb;
        int nr = node0 + r;
        if (nr < n) {
            Hout[(size_t)nr * M + tc]      = Ha;
            Hout[(size_t)nr * M + tc + 64] = Hb;
        }
    }

    // ---- attention score: a = tanh(H @ w1^T), score = a . w2 ----
    const int tt = tid & 15;                // 16 t-threads per node
    const int nd = tid >> 4;                // 0..31 node
    float part = 0.f;
    for (int c4 = 0; c4 < 4; c4++) {        // 4 chunks of 32 rows of w1
        __syncthreads();                    // previous sbuf readers done / sH visible
        const int t0 = c4 * 32;
        for (int i = tid; i < 32 * M; i += TB) {
            int tl = i >> 7, m = i & 127;
            sbuf[m * 33 + tl] = w1[(size_t)(t0 + tl) * M + m];   // transposed, pad 33
        }
        __syncthreads();
        #pragma unroll
        for (int u = 0; u < 2; u++) {
            int tl = tt * 2 + u;
            float dot = 0.f;
            #pragma unroll 8
            for (int m = 0; m < M; m++)
                dot = fmaf(sH[nd][m], sbuf[m * 33 + tl], dot);
            part += tanhf(dot) * w2[t0 + tl];
        }
    }
    // reduce 16 partials per node (lanes 0-15 / 16-31 are one node each)
    #pragma unroll
    for (int off = 8; off; off >>= 1)
        part += __shfl_down_sync(0xffffffffu, part, off, 16);
    if (tt == 0) {
        int nr = node0 + nd;
        if (nr < n) scores[nr] = part;
    }
}

// ---------------------------------------------------------------------------
// Kernel 2: per-graph segment softmax + weighted pooling. batch is sorted, so
// block g binary-searches its node range; no atomics.
// ---------------------------------------------------------------------------
__global__ __launch_bounds__(128)
void pool_kernel(const float* __restrict__ H,
                 const float* __restrict__ scores,
                 const void* __restrict__ batch,
                 int n,
                 float* __restrict__ out)
{
    const int gidx = blockIdx.x;
    const int tid  = threadIdx.x;           // 0..127 == m
    const int is64 = g_is64;

    // lower_bound(batch, gidx) and lower_bound(batch, gidx+1)
    int start, end;
    {
        int lo = 0, hi = n;
        while (lo < hi) { int mid = (lo + hi) >> 1; if (batch_at(batch, mid, is64) < gidx) lo = mid + 1; else hi = mid; }
        start = lo;
        hi = n;
        while (lo < hi) { int mid = (lo + hi) >> 1; if (batch_at(batch, mid, is64) < gidx + 1) lo = mid + 1; else hi = mid; }
        end = lo;
    }

    if (start >= end) { out[(size_t)gidx * M + tid] = 0.f; return; }

    __shared__ float red[128];

    // segment max
    float mx = -INFINITY;
    for (int i = start + tid; i < end; i += 128) mx = fmaxf(mx, scores[i]);
    red[tid] = mx; __syncthreads();
    #pragma unroll
    for (int s = 64; s; s >>= 1) { if (tid < s) red[tid] = fmaxf(red[tid], red[tid + s]); __syncthreads(); }
    mx = red[0]; __syncthreads();

    // segment sum of exp
    float sm = 0.f;
    for (int i = start + tid; i < end; i += 128) sm += expf(scores[i] - mx);
    red[tid] = sm; __syncthreads();
    #pragma unroll
    for (int s = 64; s; s >>= 1) { if (tid < s) red[tid] += red[tid + s]; __syncthreads(); }
    sm = red[0];
    const float inv = 1.f / (sm + 1e-16f);

    // weighted sum of H (thread = column m, coalesced rows)
    float acc = 0.f;
    for (int i = start; i < end; i++) {
        float w = expf(scores[i] - mx);
        acc = fmaf(w, H[(size_t)i * M + tid], acc);
    }
    out[(size_t)gidx * M + tid] = acc * inv;
}

// ---------------------------------------------------------------------------
extern "C" void kernel_launch(void* const* d_in, const int* in_sizes, int n_in,
                              void* d_out, int out_size)
{
    const float* x     = (const float*)d_in[0];
    const float* g     = (const float*)d_in[1];
    const float* mu    = (const float*)d_in[2];
    const float* sigma = (const float*)d_in[3];
    const float* w1    = (const float*)d_in[4];
    const float* w2    = (const float*)d_in[5];
    const void*  batch = d_in[6];

    int n = in_sizes[0] / F;
    if (n > NMAX) n = NMAX;
    int num_graphs = out_size / M;

    float* Hg; cudaGetSymbolAddress((void**)&Hg, g_H);
    float* Sg; cudaGetSymbolAddress((void**)&Sg, g_scores);

    node_kernel<<<(n + NODES - 1) / NODES, TB>>>(x, g, mu, sigma, w1, w2, Hg, Sg, n);
    sniff_kernel<<<1, 1>>>((const int*)batch, n);
    pool_kernel<<<num_graphs, 128>>>(Hg, Sg, batch, n, (float*)d_out);
}

// round 2
// speedup vs baseline: 1.0003x; 1.0003x over previous
#include <cuda_runtime.h>
#include <math.h>

// Problem constants (dataset is fixed)
#define NMAX   200000
#define F      256
#define KGM    8         // K (gaussian mixture components)
#define M      128
#define KM     1024      // K*M
#define ATT    128

// kernel-1 tiling
#define TB     512       // threads per block
#define NODES  32        // nodes per block
#define KC     4         // k-chunk of g held in smem

// scratch (static device allocations are the sanctioned scratch mechanism)
__device__ float g_H[(size_t)NMAX * M];      // H[n, m]
__device__ float g_scores[NMAX];             // per-node attention score
__device__ int   g_is64;                     // batch dtype flag

// ---------------------------------------------------------------------------
// batch dtype sniffer: if batch is int64, int32-word at index n-1 (odd) is the
// high word of element (n-1)/2 == 0. If int32, it's the max graph id (!=0).
// ---------------------------------------------------------------------------
__global__ void sniff_kernel(const int* __restrict__ batch32, int n) {
    g_is64 = (batch32[n - 1] == 0) ? 1 : 0;
}

__device__ __forceinline__ int batch_at(const void* b, int i, int is64) {
    if (is64) return (int)((const long long*)b)[i];
    return ((const int*)b)[i];
}

// ---------------------------------------------------------------------------
// Kernel 1: per-node fused compute.
//   out[n,1024] = x[n,:] @ g            (fp32 GEMM, 32 nodes x 1024 cols/block)
//   gauss chain -> H[n,128]
//   a = tanh(H @ w1^T); score = a . w2
// Thread map (GEMM): tc = tid&63 (64 col threads), tn = tid>>6 (8 groups of 4
// rows). Thread owns cols {tc + 64*j, j=0..15}; since col = k*128+m, that is
// exactly k=0..7 for m=tc (j even) and m=tc+64 (j odd) -> gaussian sum over K
// is thread-local.
// ---------------------------------------------------------------------------
__global__ __launch_bounds__(TB, 1)
void node_kernel(const float* __restrict__ x,
                 const float* __restrict__ g,
                 const float* __restrict__ mu,
                 const float* __restrict__ sigma,
                 const float* __restrict__ w1,
                 const float* __restrict__ w2,
                 float* __restrict__ Hout,
                 float* __restrict__ scores,
                 int n)
{
    __shared__ float sbuf[4352];            // g chunk [KC][1024] (16KB) reused as w1 chunk [128][33]
    __shared__ float sx[NODES][KC];
    __shared__ float sH[NODES][M];

    const int tid = threadIdx.x;
    const int tc  = tid & 63;
    const int tn  = tid >> 6;               // 0..7
    const int node0 = blockIdx.x * NODES;

    float acc[4][16];
    #pragma unroll
    for (int ri = 0; ri < 4; ri++)
        #pragma unroll
        for (int j = 0; j < 16; j++) acc[ri][j] = 0.f;

    // ---- GEMM: out = x @ g over 64 k-chunks of KC=4 ----
    for (int kk = 0; kk < F; kk += KC) {
        __syncthreads();
        {   // load g chunk: KC*1024 floats = 1024 float4
            const float4* gsrc = (const float4*)(g + (size_t)kk * KM);
            float4* dst = (float4*)sbuf;
            #pragma unroll
            for (int i = 0; i < (KC * KM) / 4 / TB; i++)
                dst[tid + i * TB] = gsrc[tid + i * TB];
        }
        if (tid < NODES * KC) {             // load x tile 32 x 4
            int r = tid / KC, c = tid % KC;
            int nr = node0 + r;
            sx[r][c] = (nr < n) ? x[(size_t)nr * F + kk + c] : 0.f;
        }
        __syncthreads();

        #pragma unroll
        for (int k = 0; k < KC; k++) {
            float xv[4];
            #pragma unroll
            for (int ri = 0; ri < 4; ri++) xv[ri] = sx[tn * 4 + ri][k];
            float gv[16];
            #pragma unroll
            for (int j = 0; j < 16; j++) gv[j] = sbuf[k * KM + tc + 64 * j];
            #pragma unroll
            for (int ri = 0; ri < 4; ri++)
                #pragma unroll
                for (int j = 0; j < 16; j++)
                    acc[ri][j] = fmaf(xv[ri], gv[j], acc[ri][j]);
        }
    }

    // ---- Gaussian chain -> H (thread-local over K) ----
    float muv[16], s2v[16];
    #pragma unroll
    for (int j = 0; j < 16; j++) {
        int kk2 = j >> 1;
        int m   = tc + 64 * (j & 1);
        float s = sigma[kk2 * M + m];
        muv[j] = mu[kk2 * M + m];
        s2v[j] = 1e-15f + s * s;
    }
    #pragma unroll
    for (int ri = 0; ri < 4; ri++) {
        float Ha = 0.f, Hb = 0.f;
        #pragma unroll
        for (int j = 0; j < 16; j++) {
            float o = acc[ri][j];
            float d = o - muv[j];
            float gs = expf(-0.5f * d * d / s2v[j]);
            if (j & 1) Hb = fmaf(o, gs, Hb);
            else       Ha = fmaf(o, gs, Ha);
        }
        int r = tn * 4 + ri;
        sH[r][tc]      = Ha;
        sH[r][tc + 64] = Hb;
        int nr = node0 + r;
        if (nr < n) {
            Hout[(size_t)nr * M + tc]      = Ha;
            Hout[(size_t)nr * M + tc + 64] = Hb;
        }
    }

    // ---- attention score: a = tanh(H @ w1^T), score = a . w2 ----
    const int tt = tid & 15;                // 16 t-threads per node
    const int nd = tid >> 4;                // 0..31 node
    float part = 0.f;
    for (int c4 = 0; c4 < 4; c4++) {        // 4 chunks of 32 rows of w1
        __syncthreads();                    // previous sbuf readers done / sH visible
        const int t0 = c4 * 32;
        for (int i = tid; i < 32 * M; i += TB) {
            int tl = i >> 7, m = i & 127;
            sbuf[m * 33 + tl] = w1[(size_t)(t0 + tl) * M + m];   // transposed, pad 33
        }
        __syncthreads();
        #pragma unroll
        for (int u = 0; u < 2; u++) {
            int tl = tt * 2 + u;
            float dot = 0.f;
            #pragma unroll 8
            for (int m = 0; m < M; m++)
                dot = fmaf(sH[nd][m], sbuf[m * 33 + tl], dot);
            part += tanhf(dot) * w2[t0 + tl];
        }
    }
    // reduce 16 partials per node (lanes 0-15 / 16-31 are one node each)
    #pragma unroll
    for (int off = 8; off; off >>= 1)
        part += __shfl_down_sync(0xffffffffu, part, off, 16);
    if (tt == 0) {
        int nr = node0 + nd;
        if (nr < n) scores[nr] = part;
    }
}

// ---------------------------------------------------------------------------
// Kernel 2: per-graph segment softmax + weighted pooling. batch is sorted, so
// block g binary-searches its node range; no atomics.
// ---------------------------------------------------------------------------
__global__ __launch_bounds__(128)
void pool_kernel(const float* __restrict__ H,
                 const float* __restrict__ scores,
                 const void* __restrict__ batch,
                 int n,
                 float* __restrict__ out)
{
    const int gidx = blockIdx.x;
    const int tid  = threadIdx.x;           // 0..127 == m
    const int is64 = g_is64;

    // lower_bound(batch, gidx) and lower_bound(batch, gidx+1)
    int start, end;
    {
        int lo = 0, hi = n;
        while (lo < hi) { int mid = (lo + hi) >> 1; if (batch_at(batch, mid, is64) < gidx) lo = mid + 1; else hi = mid; }
        start = lo;
        hi = n;
        while (lo < hi) { int mid = (lo + hi) >> 1; if (batch_at(batch, mid, is64) < gidx + 1) lo = mid + 1; else hi = mid; }
        end = lo;
    }

    if (start >= end) { out[(size_t)gidx * M + tid] = 0.f; return; }

    __shared__ float red[128];

    // segment max
    float mx = -INFINITY;
    for (int i = start + tid; i < end; i += 128) mx = fmaxf(mx, scores[i]);
    red[tid] = mx; __syncthreads();
    #pragma unroll
    for (int s = 64; s; s >>= 1) { if (tid < s) red[tid] = fmaxf(red[tid], red[tid + s]); __syncthreads(); }
    mx = red[0]; __syncthreads();

    // segment sum of exp
    float sm = 0.f;
    for (int i = start + tid; i < end; i += 128) sm += expf(scores[i] - mx);
    red[tid] = sm; __syncthreads();
    #pragma unroll
    for (int s = 64; s; s >>= 1) { if (tid < s) red[tid] += red[tid + s]; __syncthreads(); }
    sm = red[0];
    const float inv = 1.f / (sm + 1e-16f);

    // weighted sum of H (thread = column m, coalesced rows)
    float acc = 0.f;
    for (int i = start; i < end; i++) {
        float w = expf(scores[i] - mx);
        acc = fmaf(w, H[(size_t)i * M + tid], acc);
    }
    out[(size_t)gidx * M + tid] = acc * inv;
}

// ---------------------------------------------------------------------------
extern "C" void kernel_launch(void* const* d_in, const int* in_sizes, int n_in,
                              void* d_out, int out_size)
{
    const float* x     = (const float*)d_in[0];
    const float* g     = (const float*)d_in[1];
    const float* mu    = (const float*)d_in[2];
    const float* sigma = (const float*)d_in[3];
    const float* w1    = (const float*)d_in[4];
    const float* w2    = (const float*)d_in[5];
    const void*  batch = d_in[6];

    int n = in_sizes[0] / F;
    if (n > NMAX) n = NMAX;
    int num_graphs = out_size / M;

    float* Hg; cudaGetSymbolAddress((void**)&Hg, g_H);
    float* Sg; cudaGetSymbolAddress((void**)&Sg, g_scores);

    node_kernel<<<(n + NODES - 1) / NODES, TB>>>(x, g, mu, sigma, w1, w2, Hg, Sg, n);
    sniff_kernel<<<1, 1>>>((const int*)batch, n);
    pool_kernel<<<num_graphs, 128>>>(Hg, Sg, batch, n, (float*)d_out);
}